// round 14
// baseline (speedup 1.0000x reference)
#include <cuda_runtime.h>
#include <math.h>

// ---------------- problem constants ----------------
#define N_CAM   2
#define PH      96
#define PW      144
#define NPTS    200
#define MIN_D   1.0f
#define MAX_D   4000.0f
#define VD      32
#define VH      128
#define VW      384
#define VOXELSZ 2.5f

#define DHW   (VD*VH*VW)
#define HW    (VH*VW)
#define PHW   (PH*PW)                             // pixels per camera = 13824
#define NRAYS (N_CAM*PH*PW)
#define STEP_D ((MAX_D - MIN_D) / (float)(NPTS - 1))

#define HX (VOXELSZ * (VW - 1) * 0.5f)
#define HY (VOXELSZ * (VH - 1) * 0.5f)
#define HZ (VOXELSZ * (VD - 1) * 0.5f)

#define THREADS    256
// Ray blocks (432):
//   split : 64 rays  x 4 chunks (warp w: chunk w&3, rays (w>>2)*32+lane)
//   merged: 32 pixels x 8 chunks (warp w: chunk w, pixel = lane)  — ALL blocks work
#define RAY_BLOCKS (NRAYS / 64)                   // 432
#define NCOL4      (HW / 4)                       // 12288
#define BEV_BLOCKS ((NCOL4 * 2) / THREADS)        // 96 (2 threads/column)
#define NBLOCKS    (RAY_BLOCKS + BEV_BLOCKS)      // 528

// global accumulators (reset by the last block each replay)
__device__ float    g_accum[3] = {0.0f, 0.0f, 0.0f};
__device__ unsigned g_count = 0;

__device__ __forceinline__ float huber01(float x, float y) {
    float d = x - y;
    float v = fmaf(d * d, 100.0f, 1.0f);
    return (sqrtf(v) - 1.0f) * 0.1f;
}

// ---------------- shared march body ----------------
// Setup + slab + chunked march; camera params already in registers.
// LPRSH = log2(chunks per ray).
template<int LPRSH>
__device__ __forceinline__ void march_body(
    int idx, int sub,
    float fx, float fy, float px, float py,
    float R0, float R1, float R2, float R3, float R4,
    float R5, float R6, float R7, float R8,
    float Tx, float Ty, float Tz,
    const float* __restrict__ dens, const float* __restrict__ cols,
    float& fr, float& fg, float& fb, float& trans)
{
    constexpr int LPR = 1 << LPRSH;

    int w = idx % PW;
    int h = idx / PW;

    float dcx = ((float)w + 0.5f - px) / fx;
    float dcy = ((float)h + 0.5f - py) / fy;

    float dx = dcx*R0 + dcy*R1 + R2;
    float dy = dcx*R3 + dcy*R4 + R5;
    float dz = dcx*R6 + dcy*R7 + R8;
    float ox = -(Tx*R0 + Ty*R1 + Tz*R2);
    float oy = -(Tx*R3 + Ty*R4 + Tz*R5);
    float oz = -(Tx*R6 + Ty*R7 + Tz*R8);

    // grid-space linear form: g_axis(t) = A + B*t (slab test AND samples)
    const float cx = 0.5f * (VW - 1), cy = 0.5f * (VH - 1), cz = 0.5f * (VD - 1);
    float Ax = ox / HX * cx + cx, Bx = dx / HX * cx;
    float Ay = oy / HY * cy + cy, By = dy / HY * cy;
    float Az = oz / HZ * cz + cz, Bz = dz / HZ * cz;

    float tmin = MIN_D, tmax = MAX_D;
    {
        const float lo = -1.001f, hi = (float)VW + 0.001f;
        if (fabsf(Bx) > 1e-20f) {
            float rB = __fdividef(1.0f, Bx);
            float t1 = (lo - Ax) * rB, t2 = (hi - Ax) * rB;
            tmin = fmaxf(tmin, fminf(t1, t2)); tmax = fminf(tmax, fmaxf(t1, t2));
        } else if (Ax <= lo || Ax >= hi) { tmax = tmin - 1.0f; }
    }
    {
        const float lo = -1.001f, hi = (float)VH + 0.001f;
        if (fabsf(By) > 1e-20f) {
            float rB = __fdividef(1.0f, By);
            float t1 = (lo - Ay) * rB, t2 = (hi - Ay) * rB;
            tmin = fmaxf(tmin, fminf(t1, t2)); tmax = fminf(tmax, fmaxf(t1, t2));
        } else if (Ay <= lo || Ay >= hi) { tmax = tmin - 1.0f; }
    }
    {
        const float lo = -1.001f, hi = (float)VD + 0.001f;
        if (fabsf(Bz) > 1e-20f) {
            float rB = __fdividef(1.0f, Bz);
            float t1 = (lo - Az) * rB, t2 = (hi - Az) * rB;
            tmin = fmaxf(tmin, fminf(t1, t2)); tmax = fminf(tmax, fmaxf(t1, t2));
        } else if (Az <= lo || Az >= hi) { tmax = tmin - 1.0f; }
    }

    int i0 = 0, i1 = -1;
    if (tmax >= tmin) {
        i0 = (int)ceilf ((tmin - MIN_D) / STEP_D - 1e-4f);
        i1 = (int)floorf((tmax - MIN_D) / STEP_D + 1e-4f);
        if (i0 < 0) i0 = 0;
        if (i1 > NPTS - 1) i1 = NPTS - 1;
    }

    int nsamp = i1 - i0 + 1;                     // may be <= 0
    int chunk = (nsamp + LPR - 1) >> LPRSH;      // per-chunk count (>=0)
    int s0 = i0 + sub * chunk;
    int s1 = s0 + chunk - 1;
    if (s1 > i1) s1 = i1;

    trans = 1.0f;
    fr = 0.0f; fg = 0.0f; fb = 0.0f;

    for (int i = s0; i <= s1; ++i) {
        float t  = fmaf((float)i, STEP_D, MIN_D);
        float gx = fmaf(t, Bx, Ax);
        float gy = fmaf(t, By, Ay);
        float gz = fmaf(t, Bz, Az);

        float x0f = floorf(gx), y0f = floorf(gy), z0f = floorf(gz);
        float frx = gx - x0f, fry = gy - y0f, frz = gz - z0f;
        int ix0 = (int)x0f, iy0 = (int)y0f, iz0 = (int)z0f;

        float wx0 = (ix0     >= 0 && ix0     < VW) ? 1.0f - frx : 0.0f;
        float wx1 = (ix0 + 1 >= 0 && ix0 + 1 < VW) ? frx        : 0.0f;
        float wy0 = (iy0     >= 0 && iy0     < VH) ? 1.0f - fry : 0.0f;
        float wy1 = (iy0 + 1 >= 0 && iy0 + 1 < VH) ? fry        : 0.0f;
        float wz0 = (iz0     >= 0 && iz0     < VD) ? 1.0f - frz : 0.0f;
        float wz1 = (iz0 + 1 >= 0 && iz0 + 1 < VD) ? frz        : 0.0f;

        int x0 = min(max(ix0,     0), VW - 1);
        int x1 = min(max(ix0 + 1, 0), VW - 1);
        int y0 = min(max(iy0,     0), VH - 1) * VW;
        int y1 = min(max(iy0 + 1, 0), VH - 1) * VW;
        int z0 = min(max(iz0,     0), VD - 1) * HW;
        int z1 = min(max(iz0 + 1, 0), VD - 1) * HW;

        int f000 = z0 + y0 + x0, f001 = z0 + y0 + x1;
        int f010 = z0 + y1 + x0, f011 = z0 + y1 + x1;
        int f100 = z1 + y0 + x0, f101 = z1 + y0 + x1;
        int f110 = z1 + y1 + x0, f111 = z1 + y1 + x1;

        float w000 = wz0*wy0*wx0, w001 = wz0*wy0*wx1;
        float w010 = wz0*wy1*wx0, w011 = wz0*wy1*wx1;
        float w100 = wz1*wy0*wx0, w101 = wz1*wy0*wx1;
        float w110 = wz1*wy1*wx0, w111 = wz1*wy1*wx1;

        float d000 = __ldg(dens + f000), d001 = __ldg(dens + f001);
        float d010 = __ldg(dens + f010), d011 = __ldg(dens + f011);
        float d100 = __ldg(dens + f100), d101 = __ldg(dens + f101);
        float d110 = __ldg(dens + f110), d111 = __ldg(dens + f111);

        const float* cr = cols;
        const float* cg = cols + DHW;
        const float* cb = cols + 2*DHW;
        float r000 = __ldg(cr + f000), r001 = __ldg(cr + f001);
        float r010 = __ldg(cr + f010), r011 = __ldg(cr + f011);
        float r100 = __ldg(cr + f100), r101 = __ldg(cr + f101);
        float r110 = __ldg(cr + f110), r111 = __ldg(cr + f111);
        float g000 = __ldg(cg + f000), g001 = __ldg(cg + f001);
        float g010 = __ldg(cg + f010), g011 = __ldg(cg + f011);
        float g100 = __ldg(cg + f100), g101 = __ldg(cg + f101);
        float g110 = __ldg(cg + f110), g111 = __ldg(cg + f111);
        float b000 = __ldg(cb + f000), b001 = __ldg(cb + f001);
        float b010 = __ldg(cb + f010), b011 = __ldg(cb + f011);
        float b100 = __ldg(cb + f100), b101 = __ldg(cb + f101);
        float b110 = __ldg(cb + f110), b111 = __ldg(cb + f111);

        float ad = w000*d000 + w001*d001 + w010*d010 + w011*d011
                 + w100*d100 + w101*d101 + w110*d110 + w111*d111;
        float ar = w000*r000 + w001*r001 + w010*r010 + w011*r011
                 + w100*r100 + w101*r101 + w110*r110 + w111*r111;
        float ag = w000*g000 + w001*g001 + w010*g010 + w011*g011
                 + w100*g100 + w101*g101 + w110*g110 + w111*g111;
        float ab = w000*b000 + w001*b001 + w010*b010 + w011*b011
                 + w100*b100 + w101*b101 + w110*b110 + w111*b111;

        float wgt = ad * trans;
        fr = fmaf(wgt, ar, fr);
        fg = fmaf(wgt, ag, fg);
        fb = fmaf(wgt, ab, fb);
        trans *= (1.0f - ad);
    }
}

__global__ void __launch_bounds__(THREADS)
fused_loss_kernel(
    const float* __restrict__ dens,   // (VD,VH,VW)
    const float* __restrict__ cols,   // (3,VD,VH,VW)
    const float* __restrict__ tsil,   // (N_CAM,PH,PW)
    const float* __restrict__ timg,   // (N_CAM,PH,PW,3)
    const float* __restrict__ focal,
    const float* __restrict__ princ,
    const float* __restrict__ Rm,
    const float* __restrict__ Tv,
    float* __restrict__ out)
{
    // exchange buffers: flat [256] = sub*NP + p (merged NP=32, split NP=64)
    __shared__ float s_fr[256], s_fg[256], s_fb[256], s_tr[256];
    __shared__ float s_sil[64];       // silhouette targets
    __shared__ float s_img[192];      // image targets
    __shared__ float s_a[THREADS/32], s_b[THREADS/32];
    __shared__ bool  s_last;

    const int tid  = threadIdx.x;
    const int lane = tid & 31;
    const int warp = tid >> 5;

    if (blockIdx.x < RAY_BLOCKS) {
        int rb = blockIdx.x;

        // ---- round 0: ALL camera params, vectorized, into registers ----
        float4 f4 = __ldg((const float4*)focal);        // fx0 fy0 fx1 fy1
        float4 p4 = __ldg((const float4*)princ);        // px0 py0 px1 py1
        float4 r0 = __ldg((const float4*)(Rm));         // R[0..3]
        float4 r1 = __ldg((const float4*)(Rm + 4));     // R[4..7]
        float4 r2 = __ldg((const float4*)(Rm + 8));     // R[8..11]
        float4 r3 = __ldg((const float4*)(Rm + 12));    // R[12..15]
        float2 r4 = __ldg((const float2*)(Rm + 16));    // R[16..17]
        float4 t4 = __ldg((const float4*)(Tv));         // T[0..3]
        float2 t2 = __ldg((const float2*)(Tv + 4));     // T[4..5]

        // ---- same-camera predicate from registers ----
        bool same = (f4.x == f4.z) && (f4.y == f4.w)
                 && (p4.x == p4.z) && (p4.y == p4.w)
                 && (r0.x == r2.y) && (r0.y == r2.z) && (r0.z == r2.w)
                 && (r0.w == r3.x) && (r1.x == r3.y) && (r1.y == r3.z)
                 && (r1.z == r3.w) && (r1.w == r4.x) && (r2.x == r4.y)
                 && (t4.x == t4.w) && (t4.y == t2.x) && (t4.z == t2.y);

        float csum = 0.0f, ssum = 0.0f;

        if (same) {
            // ======== MERGED: 32 pixels x 8 chunks, all blocks active ========
            // prefetch targets (coalesced), consumed after the exchange sync
            if (tid < 32) {
                s_sil[tid]      = __ldg(tsil + rb * 32 + tid);
                s_sil[32 + tid] = __ldg(tsil + PHW + rb * 32 + tid);
            }
            if (tid < 96) {
                s_img[tid]      = __ldg(timg + rb * 96 + tid);
                s_img[96 + tid] = __ldg(timg + (size_t)PHW * 3 + rb * 96 + tid);
            }

            int p   = lane;                       // pixel-in-block 0..31
            int sub = warp;                       // chunk 0..7
            int pix = rb * 32 + p;

            float fr, fg, fb, tr;
            march_body<3>(pix, sub,
                          f4.x, f4.y, p4.x, p4.y,
                          r0.x, r0.y, r0.z, r0.w, r1.x, r1.y, r1.z, r1.w, r2.x,
                          t4.x, t4.y, t4.z,
                          dens, cols, fr, fg, fb, tr);
            int e = sub * 32 + p;
            s_fr[e] = fr; s_fg[e] = fg; s_fb[e] = fb; s_tr[e] = tr;
            __syncthreads();

            if (tid < 32) {
                int pp = tid;
                float fr2 = s_fr[pp], fg2 = s_fg[pp],
                      fb2 = s_fb[pp], tr2 = s_tr[pp];
                #pragma unroll
                for (int s = 1; s < 8; ++s) {     // sequential compose
                    int k = s * 32 + pp;
                    fr2 = fmaf(tr2, s_fr[k], fr2);
                    fg2 = fmaf(tr2, s_fg[k], fg2);
                    fb2 = fmaf(tr2, s_fb[k], fb2);
                    tr2 *= s_tr[k];
                }
                float opacity = 1.0f - tr2;
                ssum = huber01(opacity, s_sil[pp]) + huber01(opacity, s_sil[32 + pp]);
                csum = huber01(fr2, s_img[pp*3+0]) + huber01(fg2, s_img[pp*3+1])
                     + huber01(fb2, s_img[pp*3+2])
                     + huber01(fr2, s_img[96+pp*3+0]) + huber01(fg2, s_img[96+pp*3+1])
                     + huber01(fb2, s_img[96+pp*3+2]);
            }
        } else {
            // ======== SPLIT: 64 rays x 4 chunks (R13 proven path) ========
            if (tid < 64)
                s_sil[tid] = __ldg(tsil + rb * 64 + tid);
            if (tid < 192)
                s_img[tid] = __ldg(timg + (size_t)rb * 192 + tid);

            int p   = ((warp >> 2) << 5) | lane;  // ray-in-block 0..63
            int sub = warp & 3;
            int ray = rb * 64 + p;
            int cam = ray / PHW;
            int idx = ray - cam * PHW;
            bool c1 = (cam != 0);

            float fr, fg, fb, tr;
            march_body<2>(idx, sub,
                          c1 ? f4.z : f4.x, c1 ? f4.w : f4.y,
                          c1 ? p4.z : p4.x, c1 ? p4.w : p4.y,
                          c1 ? r2.y : r0.x, c1 ? r2.z : r0.y, c1 ? r2.w : r0.z,
                          c1 ? r3.x : r0.w, c1 ? r3.y : r1.x, c1 ? r3.z : r1.y,
                          c1 ? r3.w : r1.z, c1 ? r4.x : r1.w, c1 ? r4.y : r2.x,
                          c1 ? t4.w : t4.x, c1 ? t2.x : t4.y, c1 ? t2.y : t4.z,
                          dens, cols, fr, fg, fb, tr);
            int e = sub * 64 + p;
            s_fr[e] = fr; s_fg[e] = fg; s_fb[e] = fb; s_tr[e] = tr;
            __syncthreads();

            if (tid < 64) {
                int pp = tid;
                float fr2 = s_fr[pp], fg2 = s_fg[pp],
                      fb2 = s_fb[pp], tr2 = s_tr[pp];
                #pragma unroll
                for (int s = 1; s < 4; ++s) {
                    int k = s * 64 + pp;
                    fr2 = fmaf(tr2, s_fr[k], fr2);
                    fg2 = fmaf(tr2, s_fg[k], fg2);
                    fb2 = fmaf(tr2, s_fb[k], fb2);
                    tr2 *= s_tr[k];
                }
                float opacity = 1.0f - tr2;
                ssum = huber01(opacity, s_sil[pp]);
                csum = huber01(fr2, s_img[pp*3+0]) + huber01(fg2, s_img[pp*3+1])
                     + huber01(fb2, s_img[pp*3+2]);
            }
        }

        // block reduce, then one atomic per block
        #pragma unroll
        for (int o = 16; o > 0; o >>= 1) {
            csum += __shfl_down_sync(0xffffffffu, csum, o);
            ssum += __shfl_down_sync(0xffffffffu, ssum, o);
        }
        if (lane == 0) { s_a[warp] = csum; s_b[warp] = ssum; }
        __syncthreads();
        if (warp == 0) {
            float a = (lane < THREADS/32) ? s_a[lane] : 0.0f;
            float b = (lane < THREADS/32) ? s_b[lane] : 0.0f;
            #pragma unroll
            for (int o = 4; o > 0; o >>= 1) {
                a += __shfl_down_sync(0xffffffffu, a, o);
                b += __shfl_down_sync(0xffffffffu, b, o);
            }
            if (lane == 0) {
                atomicAdd(&g_accum[0], a);
                atomicAdd(&g_accum[1], b);
            }
        }
    } else {
        // -------- BEV blocks: mean |max_z dens|, 2 threads per column --------
        int gb    = (blockIdx.x - RAY_BLOCKS) * (THREADS / 32) + warp;
        int cidx  = gb * 16 + (lane & 15);       // float4 column index (< NCOL4)
        int zbase = (lane >> 4) * 16;            // 0 or 16

        const float4* d4 = (const float4*)dens;
        float4 m = __ldg(d4 + cidx + zbase * NCOL4);
        #pragma unroll
        for (int z = 1; z < 16; ++z) {
            float4 v = __ldg(d4 + cidx + (zbase + z) * NCOL4);
            m.x = fmaxf(m.x, v.x); m.y = fmaxf(m.y, v.y);
            m.z = fmaxf(m.z, v.z); m.w = fmaxf(m.w, v.w);
        }
        m.x = fmaxf(m.x, __shfl_xor_sync(0xffffffffu, m.x, 16));
        m.y = fmaxf(m.y, __shfl_xor_sync(0xffffffffu, m.y, 16));
        m.z = fmaxf(m.z, __shfl_xor_sync(0xffffffffu, m.z, 16));
        m.w = fmaxf(m.w, __shfl_xor_sync(0xffffffffu, m.w, 16));

        float bsum = (lane < 16)
                   ? (fabsf(m.x) + fabsf(m.y) + fabsf(m.z) + fabsf(m.w))
                   : 0.0f;
        #pragma unroll
        for (int o = 8; o > 0; o >>= 1)
            bsum += __shfl_down_sync(0xffffffffu, bsum, o);
        if (lane == 0) s_a[warp] = bsum;
        __syncthreads();
        if (warp == 0) {
            float a = (lane < THREADS/32) ? s_a[lane] : 0.0f;
            #pragma unroll
            for (int o = 4; o > 0; o >>= 1)
                a += __shfl_down_sync(0xffffffffu, a, o);
            if (lane == 0)
                atomicAdd(&g_accum[2], a);
        }
    }

    // ---------------- last block finalizes ----------------
    if (tid == 0) {
        __threadfence();
        unsigned prev = atomicAdd(&g_count, 1u);
        s_last = (prev == NBLOCKS - 1);
    }
    __syncthreads();

    if (s_last && tid == 0) {
        float a = g_accum[0];
        float b = g_accum[1];
        float c = g_accum[2];
        out[0] = a * (1.0f / (float)(NRAYS * 3));
        out[1] = b * (1.0f / (float)NRAYS);
        out[2] = c * (1.0f / (float)HW);
        // reset for next graph replay
        g_accum[0] = 0.0f;
        g_accum[1] = 0.0f;
        g_accum[2] = 0.0f;
        g_count = 0;
    }
}

extern "C" void kernel_launch(void* const* d_in, const int* in_sizes, int n_in,
                              void* d_out, int out_size) {
    const float* dens  = (const float*)d_in[0];
    const float* cols  = (const float*)d_in[1];
    const float* tsil  = (const float*)d_in[2];
    const float* timg  = (const float*)d_in[3];
    const float* focal = (const float*)d_in[4];
    const float* princ = (const float*)d_in[5];
    const float* Rm    = (const float*)d_in[6];
    const float* Tv    = (const float*)d_in[7];
    float* out = (float*)d_out;

    fused_loss_kernel<<<NBLOCKS, THREADS>>>(dens, cols, tsil, timg,
                                            focal, princ, Rm, Tv, out);
}

// round 15
// speedup vs baseline: 1.2444x; 1.2444x over previous
#include <cuda_runtime.h>
#include <math.h>

// ---------------- problem constants ----------------
#define N_CAM   2
#define PH      96
#define PW      144
#define NPTS    200
#define MIN_D   1.0f
#define MAX_D   4000.0f
#define VD      32
#define VH      128
#define VW      384
#define VOXELSZ 2.5f

#define DHW   (VD*VH*VW)
#define HW    (VH*VW)
#define PHW   (PH*PW)                             // pixels per camera = 13824
#define NRAYS (N_CAM*PH*PW)
#define STEP_D ((MAX_D - MIN_D) / (float)(NPTS - 1))

#define HX (VOXELSZ * (VW - 1) * 0.5f)
#define HY (VOXELSZ * (VH - 1) * 0.5f)
#define HZ (VOXELSZ * (VD - 1) * 0.5f)

#define THREADS    256
// Each ray block covers 64 rays: warp w handles chunk (w&3) of ray group (w>>2).
// Warp lanes = 32 CONSECUTIVE rays at the SAME chunk -> coalesced gathers.
#define RAY_BLOCKS        (NRAYS / 64)            // 432 (split path)
#define MERGED_RAY_BLOCKS (PHW / 64)              // 216 (merged path)
#define NCOL4      (HW / 4)                       // 12288
#define BEV_BLOCKS ((NCOL4 * 2) / THREADS)        // 96 (2 threads/column)
#define NBLOCKS    (RAY_BLOCKS + BEV_BLOCKS)      // 528

// global accumulators (reset by the last block each replay)
__device__ float    g_accum[3] = {0.0f, 0.0f, 0.0f};
__device__ unsigned g_count = 0;

__device__ __forceinline__ float huber01(float x, float y) {
    float d = x - y;
    float v = fmaf(d * d, 100.0f, 1.0f);
    return (sqrtf(v) - 1.0f) * 0.1f;
}

// ---------------- shared march body ----------------
// Setup + slab + chunked march given camera params already in registers.
__device__ __forceinline__ void march_body(
    int idx, int sub,
    float fx, float fy, float px, float py,
    float R0, float R1, float R2, float R3, float R4,
    float R5, float R6, float R7, float R8,
    float Tx, float Ty, float Tz,
    const float* __restrict__ dens, const float* __restrict__ cols,
    float& fr, float& fg, float& fb, float& trans)
{
    int w = idx % PW;
    int h = idx / PW;

    float dcx = __fdividef((float)w + 0.5f - px, fx);
    float dcy = __fdividef((float)h + 0.5f - py, fy);

    float dx = dcx*R0 + dcy*R1 + R2;
    float dy = dcx*R3 + dcy*R4 + R5;
    float dz = dcx*R6 + dcy*R7 + R8;
    float ox = -(Tx*R0 + Ty*R1 + Tz*R2);
    float oy = -(Tx*R3 + Ty*R4 + Tz*R5);
    float oz = -(Tx*R6 + Ty*R7 + Tz*R8);

    // grid-space linear form: g_axis(t) = A + B*t (slab test AND samples)
    const float cx = 0.5f * (VW - 1), cy = 0.5f * (VH - 1), cz = 0.5f * (VD - 1);
    float Ax = ox / HX * cx + cx, Bx = dx / HX * cx;
    float Ay = oy / HY * cy + cy, By = dy / HY * cy;
    float Az = oz / HZ * cz + cz, Bz = dz / HZ * cz;

    float tmin = MIN_D, tmax = MAX_D;
    {
        const float lo = -1.001f, hi = (float)VW + 0.001f;
        if (fabsf(Bx) > 1e-20f) {
            float rB = __fdividef(1.0f, Bx);
            float t1 = (lo - Ax) * rB, t2 = (hi - Ax) * rB;
            tmin = fmaxf(tmin, fminf(t1, t2)); tmax = fminf(tmax, fmaxf(t1, t2));
        } else if (Ax <= lo || Ax >= hi) { tmax = tmin - 1.0f; }
    }
    {
        const float lo = -1.001f, hi = (float)VH + 0.001f;
        if (fabsf(By) > 1e-20f) {
            float rB = __fdividef(1.0f, By);
            float t1 = (lo - Ay) * rB, t2 = (hi - Ay) * rB;
            tmin = fmaxf(tmin, fminf(t1, t2)); tmax = fminf(tmax, fmaxf(t1, t2));
        } else if (Ay <= lo || Ay >= hi) { tmax = tmin - 1.0f; }
    }
    {
        const float lo = -1.001f, hi = (float)VD + 0.001f;
        if (fabsf(Bz) > 1e-20f) {
            float rB = __fdividef(1.0f, Bz);
            float t1 = (lo - Az) * rB, t2 = (hi - Az) * rB;
            tmin = fmaxf(tmin, fminf(t1, t2)); tmax = fminf(tmax, fmaxf(t1, t2));
        } else if (Az <= lo || Az >= hi) { tmax = tmin - 1.0f; }
    }

    int i0 = 0, i1 = -1;
    if (tmax >= tmin) {
        i0 = (int)ceilf ((tmin - MIN_D) / STEP_D - 1e-4f);
        i1 = (int)floorf((tmax - MIN_D) / STEP_D + 1e-4f);
        if (i0 < 0) i0 = 0;
        if (i1 > NPTS - 1) i1 = NPTS - 1;
    }

    int nsamp = i1 - i0 + 1;                     // may be <= 0
    int chunk = (nsamp + 3) >> 2;                // per-chunk count (>=0)
    int s0 = i0 + sub * chunk;
    int s1 = s0 + chunk - 1;
    if (s1 > i1) s1 = i1;

    trans = 1.0f;
    fr = 0.0f; fg = 0.0f; fb = 0.0f;

    // unroll 2: iteration i+1's 32 independent loads can hoist above
    // iteration i's FMA chain -> the two gather rounds overlap.
    #pragma unroll 2
    for (int i = s0; i <= s1; ++i) {
        float t  = fmaf((float)i, STEP_D, MIN_D);
        float gx = fmaf(t, Bx, Ax);
        float gy = fmaf(t, By, Ay);
        float gz = fmaf(t, Bz, Az);

        float x0f = floorf(gx), y0f = floorf(gy), z0f = floorf(gz);
        float frx = gx - x0f, fry = gy - y0f, frz = gz - z0f;
        int ix0 = (int)x0f, iy0 = (int)y0f, iz0 = (int)z0f;

        float wx0 = (ix0     >= 0 && ix0     < VW) ? 1.0f - frx : 0.0f;
        float wx1 = (ix0 + 1 >= 0 && ix0 + 1 < VW) ? frx        : 0.0f;
        float wy0 = (iy0     >= 0 && iy0     < VH) ? 1.0f - fry : 0.0f;
        float wy1 = (iy0 + 1 >= 0 && iy0 + 1 < VH) ? fry        : 0.0f;
        float wz0 = (iz0     >= 0 && iz0     < VD) ? 1.0f - frz : 0.0f;
        float wz1 = (iz0 + 1 >= 0 && iz0 + 1 < VD) ? frz        : 0.0f;

        int x0 = min(max(ix0,     0), VW - 1);
        int x1 = min(max(ix0 + 1, 0), VW - 1);
        int y0 = min(max(iy0,     0), VH - 1) * VW;
        int y1 = min(max(iy0 + 1, 0), VH - 1) * VW;
        int z0 = min(max(iz0,     0), VD - 1) * HW;
        int z1 = min(max(iz0 + 1, 0), VD - 1) * HW;

        int f000 = z0 + y0 + x0, f001 = z0 + y0 + x1;
        int f010 = z0 + y1 + x0, f011 = z0 + y1 + x1;
        int f100 = z1 + y0 + x0, f101 = z1 + y0 + x1;
        int f110 = z1 + y1 + x0, f111 = z1 + y1 + x1;

        float w000 = wz0*wy0*wx0, w001 = wz0*wy0*wx1;
        float w010 = wz0*wy1*wx0, w011 = wz0*wy1*wx1;
        float w100 = wz1*wy0*wx0, w101 = wz1*wy0*wx1;
        float w110 = wz1*wy1*wx0, w111 = wz1*wy1*wx1;

        float d000 = __ldg(dens + f000), d001 = __ldg(dens + f001);
        float d010 = __ldg(dens + f010), d011 = __ldg(dens + f011);
        float d100 = __ldg(dens + f100), d101 = __ldg(dens + f101);
        float d110 = __ldg(dens + f110), d111 = __ldg(dens + f111);

        const float* cr = cols;
        const float* cg = cols + DHW;
        const float* cb = cols + 2*DHW;
        float r000 = __ldg(cr + f000), r001 = __ldg(cr + f001);
        float r010 = __ldg(cr + f010), r011 = __ldg(cr + f011);
        float r100 = __ldg(cr + f100), r101 = __ldg(cr + f101);
        float r110 = __ldg(cr + f110), r111 = __ldg(cr + f111);
        float g000 = __ldg(cg + f000), g001 = __ldg(cg + f001);
        float g010 = __ldg(cg + f010), g011 = __ldg(cg + f011);
        float g100 = __ldg(cg + f100), g101 = __ldg(cg + f101);
        float g110 = __ldg(cg + f110), g111 = __ldg(cg + f111);
        float b000 = __ldg(cb + f000), b001 = __ldg(cb + f001);
        float b010 = __ldg(cb + f010), b011 = __ldg(cb + f011);
        float b100 = __ldg(cb + f100), b101 = __ldg(cb + f101);
        float b110 = __ldg(cb + f110), b111 = __ldg(cb + f111);

        float ad = w000*d000 + w001*d001 + w010*d010 + w011*d011
                 + w100*d100 + w101*d101 + w110*d110 + w111*d111;
        float ar = w000*r000 + w001*r001 + w010*r010 + w011*r011
                 + w100*r100 + w101*r101 + w110*r110 + w111*r111;
        float ag = w000*g000 + w001*g001 + w010*g010 + w011*g011
                 + w100*g100 + w101*g101 + w110*g110 + w111*g111;
        float ab = w000*b000 + w001*b001 + w010*b010 + w011*b011
                 + w100*b100 + w101*b101 + w110*b110 + w111*b111;

        float wgt = ad * trans;
        fr = fmaf(wgt, ar, fr);
        fg = fmaf(wgt, ag, fg);
        fb = fmaf(wgt, ab, fb);
        trans *= (1.0f - ad);
    }
}

__global__ void __launch_bounds__(THREADS)
fused_loss_kernel(
    const float* __restrict__ dens,   // (VD,VH,VW)
    const float* __restrict__ cols,   // (3,VD,VH,VW)
    const float* __restrict__ tsil,   // (N_CAM,PH,PW)
    const float* __restrict__ timg,   // (N_CAM,PH,PW,3)
    const float* __restrict__ focal,
    const float* __restrict__ princ,
    const float* __restrict__ Rm,
    const float* __restrict__ Tv,
    float* __restrict__ out)
{
    __shared__ float s_fr[4][64], s_fg[4][64], s_fb[4][64], s_tr[4][64];
    __shared__ float s_tg[8][64];     // prefetched loss targets
    __shared__ float s_a[THREADS/32], s_b[THREADS/32];
    __shared__ bool  s_last;

    const int tid  = threadIdx.x;
    const int lane = tid & 31;
    const int warp = tid >> 5;

    if (blockIdx.x < RAY_BLOCKS) {
        int rb = blockIdx.x;

        // ---- round 0: ALL camera params, vectorized, into registers ----
        float4 f4 = __ldg((const float4*)focal);        // fx0 fy0 fx1 fy1
        float4 p4 = __ldg((const float4*)princ);        // px0 py0 px1 py1
        float4 r0 = __ldg((const float4*)(Rm));         // R[0..3]
        float4 r1 = __ldg((const float4*)(Rm + 4));     // R[4..7]
        float4 r2 = __ldg((const float4*)(Rm + 8));     // R[8..11]
        float4 r3 = __ldg((const float4*)(Rm + 12));    // R[12..15]
        float2 r4 = __ldg((const float2*)(Rm + 16));    // R[16..17]
        float4 t4 = __ldg((const float4*)(Tv));         // T[0..3]
        float2 t2 = __ldg((const float2*)(Tv + 4));     // T[4..5]

        // ---- round 0: prefetch loss targets into smem (index mode-indep) ----
        if (tid < 64) {
            int x = rb * 64 + tid;                      // ray/pixel id
            s_tg[0][tid] = __ldg(tsil + x);
            const float* ti = timg + (size_t)x * 3;
            s_tg[2][tid] = __ldg(ti + 0);
            s_tg[3][tid] = __ldg(ti + 1);
            s_tg[4][tid] = __ldg(ti + 2);
            if (x + PHW < NRAYS) {                      // second-cam targets
                s_tg[1][tid] = __ldg(tsil + x + PHW);
                const float* tj = timg + (size_t)(x + PHW) * 3;
                s_tg[5][tid] = __ldg(tj + 0);
                s_tg[6][tid] = __ldg(tj + 1);
                s_tg[7][tid] = __ldg(tj + 2);
            }
        }

        // ---- same-camera predicate from registers (no extra loads) ----
        bool same = (f4.x == f4.z) && (f4.y == f4.w)
                 && (p4.x == p4.z) && (p4.y == p4.w)
                 && (r0.x == r2.y) && (r0.y == r2.z) && (r0.z == r2.w)
                 && (r0.w == r3.x) && (r1.x == r3.y) && (r1.y == r3.z)
                 && (r1.z == r3.w) && (r1.w == r4.x) && (r2.x == r4.y)
                 && (t4.x == t4.w) && (t4.y == t2.x) && (t4.z == t2.y);

        int p   = ((warp >> 2) << 5) | lane;            // ray-in-block 0..63
        int sub = warp & 3;                             // chunk index
        bool active = !same || (rb < MERGED_RAY_BLOCKS);

        if (active) {
            float fr, fg, fb, tr;
            if (same) {
                // merged: params already in registers — no post-branch loads
                int pix = rb * 64 + p;
                march_body(pix, sub,
                           f4.x, f4.y, p4.x, p4.y,
                           r0.x, r0.y, r0.z, r0.w, r1.x, r1.y, r1.z, r1.w, r2.x,
                           t4.x, t4.y, t4.z,
                           dens, cols, fr, fg, fb, tr);
            } else {
                // split: select cam-1 params via registers too
                int ray = rb * 64 + p;
                int cam = ray / PHW;
                int idx = ray - cam * PHW;
                bool c1 = (cam != 0);
                march_body(idx, sub,
                           c1 ? f4.z : f4.x, c1 ? f4.w : f4.y,
                           c1 ? p4.z : p4.x, c1 ? p4.w : p4.y,
                           c1 ? r2.y : r0.x, c1 ? r2.z : r0.y, c1 ? r2.w : r0.z,
                           c1 ? r3.x : r0.w, c1 ? r3.y : r1.x, c1 ? r3.z : r1.y,
                           c1 ? r3.w : r1.z, c1 ? r4.x : r1.w, c1 ? r4.y : r2.x,
                           c1 ? t4.w : t4.x, c1 ? t2.x : t4.y, c1 ? t2.y : t4.z,
                           dens, cols, fr, fg, fb, tr);
            }
            s_fr[sub][p] = fr; s_fg[sub][p] = fg;
            s_fb[sub][p] = fb; s_tr[sub][p] = tr;
        }
        __syncthreads();

        float csum = 0.0f, ssum = 0.0f;
        if (active && tid < 64) {
            int pp = tid;
            float fr = s_fr[0][pp], fg = s_fg[0][pp],
                  fb = s_fb[0][pp], tr = s_tr[0][pp];
            #pragma unroll
            for (int s = 1; s < 4; ++s) {               // ((0⊗1)⊗2)⊗3
                fr = fmaf(tr, s_fr[s][pp], fr);
                fg = fmaf(tr, s_fg[s][pp], fg);
                fb = fmaf(tr, s_fb[s][pp], fb);
                tr *= s_tr[s][pp];
            }
            float opacity = 1.0f - tr;
            if (same) {
                ssum = huber01(opacity, s_tg[0][pp]) + huber01(opacity, s_tg[1][pp]);
                csum = huber01(fr, s_tg[2][pp]) + huber01(fg, s_tg[3][pp])
                     + huber01(fb, s_tg[4][pp])
                     + huber01(fr, s_tg[5][pp]) + huber01(fg, s_tg[6][pp])
                     + huber01(fb, s_tg[7][pp]);
            } else {
                ssum = huber01(opacity, s_tg[0][pp]);
                csum = huber01(fr, s_tg[2][pp]) + huber01(fg, s_tg[3][pp])
                     + huber01(fb, s_tg[4][pp]);
            }
        }

        // block reduce, then one atomic per block
        #pragma unroll
        for (int o = 16; o > 0; o >>= 1) {
            csum += __shfl_down_sync(0xffffffffu, csum, o);
            ssum += __shfl_down_sync(0xffffffffu, ssum, o);
        }
        if (lane == 0) { s_a[warp] = csum; s_b[warp] = ssum; }
        __syncthreads();
        if (warp == 0) {
            float a = (lane < THREADS/32) ? s_a[lane] : 0.0f;
            float b = (lane < THREADS/32) ? s_b[lane] : 0.0f;
            #pragma unroll
            for (int o = 4; o > 0; o >>= 1) {
                a += __shfl_down_sync(0xffffffffu, a, o);
                b += __shfl_down_sync(0xffffffffu, b, o);
            }
            if (lane == 0) {
                atomicAdd(&g_accum[0], a);
                atomicAdd(&g_accum[1], b);
            }
        }
    } else {
        // -------- BEV blocks: mean |max_z dens|, 2 threads per column --------
        int gb    = (blockIdx.x - RAY_BLOCKS) * (THREADS / 32) + warp;
        int cidx  = gb * 16 + (lane & 15);       // float4 column index (< NCOL4)
        int zbase = (lane >> 4) * 16;            // 0 or 16

        const float4* d4 = (const float4*)dens;
        float4 m = __ldg(d4 + cidx + zbase * NCOL4);
        #pragma unroll
        for (int z = 1; z < 16; ++z) {
            float4 v = __ldg(d4 + cidx + (zbase + z) * NCOL4);
            m.x = fmaxf(m.x, v.x); m.y = fmaxf(m.y, v.y);
            m.z = fmaxf(m.z, v.z); m.w = fmaxf(m.w, v.w);
        }
        m.x = fmaxf(m.x, __shfl_xor_sync(0xffffffffu, m.x, 16));
        m.y = fmaxf(m.y, __shfl_xor_sync(0xffffffffu, m.y, 16));
        m.z = fmaxf(m.z, __shfl_xor_sync(0xffffffffu, m.z, 16));
        m.w = fmaxf(m.w, __shfl_xor_sync(0xffffffffu, m.w, 16));

        float bsum = (lane < 16)
                   ? (fabsf(m.x) + fabsf(m.y) + fabsf(m.z) + fabsf(m.w))
                   : 0.0f;
        #pragma unroll
        for (int o = 8; o > 0; o >>= 1)
            bsum += __shfl_down_sync(0xffffffffu, bsum, o);
        if (lane == 0) s_a[warp] = bsum;
        __syncthreads();
        if (warp == 0) {
            float a = (lane < THREADS/32) ? s_a[lane] : 0.0f;
            #pragma unroll
            for (int o = 4; o > 0; o >>= 1)
                a += __shfl_down_sync(0xffffffffu, a, o);
            if (lane == 0)
                atomicAdd(&g_accum[2], a);
        }
    }

    // ---------------- last block finalizes ----------------
    if (tid == 0) {
        __threadfence();
        unsigned prev = atomicAdd(&g_count, 1u);
        s_last = (prev == NBLOCKS - 1);
    }
    __syncthreads();

    if (s_last && tid == 0) {
        float a = g_accum[0];
        float b = g_accum[1];
        float c = g_accum[2];
        out[0] = a * (1.0f / (float)(NRAYS * 3));
        out[1] = b * (1.0f / (float)NRAYS);
        out[2] = c * (1.0f / (float)HW);
        // reset for next graph replay
        g_accum[0] = 0.0f;
        g_accum[1] = 0.0f;
        g_accum[2] = 0.0f;
        g_count = 0;
    }
}

extern "C" void kernel_launch(void* const* d_in, const int* in_sizes, int n_in,
                              void* d_out, int out_size) {
    const float* dens  = (const float*)d_in[0];
    const float* cols  = (const float*)d_in[1];
    const float* tsil  = (const float*)d_in[2];
    const float* timg  = (const float*)d_in[3];
    const float* focal = (const float*)d_in[4];
    const float* princ = (const float*)d_in[5];
    const float* Rm    = (const float*)d_in[6];
    const float* Tv    = (const float*)d_in[7];
    float* out = (float*)d_out;

    fused_loss_kernel<<<NBLOCKS, THREADS>>>(dens, cols, tsil, timg,
                                            focal, princ, Rm, Tv, out);
}